// round 12
// baseline (speedup 1.0000x reference)
#include <cuda_runtime.h>
#include <math.h>

// Problem constants (capacities for static scratch)
#define Nn   50000
#define Ee   800000
#define Gg   1024
#define Dd   64
#define DIN  9

#define SCAN_CHUNK 256
#define SCAN_NB    ((Nn + SCAN_CHUNK - 1) / SCAN_CHUNK)   // 196

// ---------------- scratch (static device globals; no allocation) ------------
static __device__ float    g_hW[Nn * Dd];     // h @ W (pre-aggregation)
static __device__ float    g_h[Nn * Dd];      // layer activations
static __device__ int      g_deg[Nn];         // in-degree (edges only)
static __device__ float    g_dinv[Nn];        // (deg+1)^-1/2
static __device__ int      g_off[Nn + 1];     // CSR offsets (by destination)
static __device__ int      g_pos[Nn];         // fill cursors
static __device__ float2   g_csr[Ee];         // (src as int bits, norm)
static __device__ int      g_bsum[SCAN_NB];   // per-chunk degree sums
static __device__ int      g_boff[SCAN_NB];   // exclusive-scanned chunk offsets
static __device__ float    g_gsum[Gg * Dd];
static __device__ unsigned g_gmax[Gg * Dd];   // order-preserving float keys
static __device__ float    g_cnt[Gg];

// Order-preserving float <-> unsigned key (init 0 == -inf)
__device__ __forceinline__ unsigned fkey(float f) {
    unsigned u = __float_as_uint(f);
    return (u & 0x80000000u) ? ~u : (u | 0x80000000u);
}
__device__ __forceinline__ float unfkey(unsigned k) {
    unsigned u = (k & 0x80000000u) ? (k ^ 0x80000000u) : ~k;
    return __uint_as_float(u);
}

// ---------------- prep kernels ----------------------------------------------

__global__ void k_init() {
    int i = blockIdx.x * blockDim.x + threadIdx.x;
    if (i < Nn) g_deg[i] = 0;
    if (i < Gg * Dd) { g_gsum[i] = 0.f; g_gmax[i] = 0u; }
    if (i < Gg) g_cnt[i] = 0.f;
}

__global__ void k_deg(const int* __restrict__ col, int e) {
    int i = blockIdx.x * blockDim.x + threadIdx.x;
    if (i < e) atomicAdd(&g_deg[col[i]], 1);
}

__global__ void k_dinv(int n) {
    int i = blockIdx.x * blockDim.x + threadIdx.x;
    if (i < n) g_dinv[i] = rsqrtf((float)g_deg[i] + 1.0f);  // +1 = self loop
}

// ---- parallel scan, phase 1: per-chunk sums (256 elems per block) ----------
__global__ void __launch_bounds__(SCAN_CHUNK) k_scan1() {
    __shared__ int ws[SCAN_CHUNK / 32];
    int i = blockIdx.x * SCAN_CHUNK + threadIdx.x;
    int v = (i < Nn) ? g_deg[i] : 0;
    int lane = threadIdx.x & 31, w = threadIdx.x >> 5;
#pragma unroll
    for (int o = 16; o > 0; o >>= 1) v += __shfl_down_sync(~0u, v, o);
    if (lane == 0) ws[w] = v;
    __syncthreads();
    if (threadIdx.x == 0) {
        int s = 0;
#pragma unroll
        for (int k = 0; k < SCAN_CHUNK / 32; k++) s += ws[k];
        g_bsum[blockIdx.x] = s;
    }
}

// ---- phase 2: exclusive scan of chunk sums (single small block) ------------
__global__ void __launch_bounds__(256) k_scan2(int e) {
    __shared__ int wsum[8];
    int lane = threadIdx.x & 31, w = threadIdx.x >> 5;
    int v = (threadIdx.x < SCAN_NB) ? g_bsum[threadIdx.x] : 0;
    int x = v;
#pragma unroll
    for (int o = 1; o < 32; o <<= 1) {
        int y = __shfl_up_sync(~0u, x, o);
        if (lane >= o) x += y;
    }
    if (lane == 31) wsum[w] = x;
    __syncthreads();
    if (w == 0 && lane < 8) {
        int ws = wsum[lane];
#pragma unroll
        for (int o = 1; o < 8; o <<= 1) {
            int y = __shfl_up_sync(0xffu, ws, o);
            if (lane >= o) ws += y;
        }
        wsum[lane] = ws;
    }
    __syncthreads();
    int excl = x - v + (w > 0 ? wsum[w - 1] : 0);
    if (threadIdx.x < SCAN_NB) g_boff[threadIdx.x] = excl;
    if (threadIdx.x == 0) g_off[Nn] = e;
}

// ---- phase 3: per-chunk exclusive scan + chunk offset -> g_off / g_pos -----
__global__ void __launch_bounds__(SCAN_CHUNK) k_scan3() {
    __shared__ int wsum[SCAN_CHUNK / 32];
    int i = blockIdx.x * SCAN_CHUNK + threadIdx.x;
    int v = (i < Nn) ? g_deg[i] : 0;
    int lane = threadIdx.x & 31, w = threadIdx.x >> 5;
    int x = v;
#pragma unroll
    for (int o = 1; o < 32; o <<= 1) {
        int y = __shfl_up_sync(~0u, x, o);
        if (lane >= o) x += y;
    }
    if (lane == 31) wsum[w] = x;
    __syncthreads();
    if (w == 0 && lane < SCAN_CHUNK / 32) {
        int ws = wsum[lane];
#pragma unroll
        for (int o = 1; o < SCAN_CHUNK / 32; o <<= 1) {
            int y = __shfl_up_sync((1u << (SCAN_CHUNK / 32)) - 1u, ws, o);
            if (lane >= o) ws += y;
        }
        wsum[lane] = ws;
    }
    __syncthreads();
    int excl = x - v + (w > 0 ? wsum[w - 1] : 0) + g_boff[blockIdx.x];
    if (i < Nn) { g_off[i] = excl; g_pos[i] = excl; }
}

__global__ void k_fill(const int* __restrict__ row, const int* __restrict__ col, int e) {
    int i = blockIdx.x * blockDim.x + threadIdx.x;
    if (i >= e) return;
    int src = row[i], dst = col[i];
    float nm = g_dinv[src] * g_dinv[dst];
    int pos = atomicAdd(&g_pos[dst], 1);
    g_csr[pos] = make_float2(__int_as_float(src), nm);
}

// ---------------- dense kernels ---------------------------------------------

// x[N,9] @ W0[9,64] -> g_hW
__global__ void k_gemm_in(const float* __restrict__ x, const float* __restrict__ W, int n) {
    int idx = blockIdx.x * blockDim.x + threadIdx.x;
    if (idx >= n * Dd) return;
    int nn = idx >> 6, d = idx & 63;
    float acc = 0.f;
#pragma unroll
    for (int k = 0; k < DIN; k++)
        acc += __ldg(&x[nn * DIN + k]) * __ldg(&W[k * Dd + d]);
    g_hW[idx] = acc;
}

// g_h[N,64] @ W[64,64] -> g_hW ; smem-tiled, 4x4 register tile per thread.
// Reads g_h via device-side symbol (never pass __device__ arrays from host).
__global__ void __launch_bounds__(256) k_gemm64(const float* __restrict__ W, int n) {
    __shared__ float sHT[64][68];  // transposed: sHT[k][r]
    __shared__ float sW[64][68];   // sW[k][d]
    int b0 = blockIdx.x * 64;

    for (int i = threadIdx.x; i < 4096; i += 256) {
        int k = i >> 6, d = i & 63;
        sW[k][d] = W[i];
    }
    for (int i = threadIdx.x; i < 4096; i += 256) {
        int r = i >> 6, k = i & 63;
        int node = b0 + r;
        sHT[k][r] = (node < n) ? g_h[node * 64 + k] : 0.f;
    }
    __syncthreads();

    int tx = threadIdx.x & 15;   // d group
    int ty = threadIdx.x >> 4;   // node group
    int r0 = ty * 4, d0 = tx * 4;

    float acc[4][4] = {};
#pragma unroll
    for (int k = 0; k < 64; k++) {
        float4 av = *(const float4*)&sHT[k][r0];
        float4 bv = *(const float4*)&sW[k][d0];
        float a[4] = {av.x, av.y, av.z, av.w};
        float b[4] = {bv.x, bv.y, bv.z, bv.w};
#pragma unroll
        for (int i = 0; i < 4; i++)
#pragma unroll
            for (int j = 0; j < 4; j++)
                acc[i][j] += a[i] * b[j];
    }

#pragma unroll
    for (int i = 0; i < 4; i++) {
        int node = b0 + r0 + i;
        if (node < n) {
            float4 v = make_float4(acc[i][0], acc[i][1], acc[i][2], acc[i][3]);
            *(float4*)&g_hW[node * 64 + d0] = v;
        }
    }
}

// ---------------- fused gather-aggregate + tanh (+ pooling) -----------------
// one warp per node; lane owns dims {2*lane, 2*lane+1}. Edge loop unrolled x4
// with all loads batched before FMAs for memory-level parallelism.
template <int POOL>
__global__ void __launch_bounds__(256) k_agg(const float* __restrict__ bias,
                                             const int* __restrict__ batch, int n) {
    int warp = (blockIdx.x * blockDim.x + threadIdx.x) >> 5;
    if (warp >= n) return;
    int lane = threadIdx.x & 31;
    int d0 = lane * 2;

    int s = g_off[warp];
    int t = g_off[warp + 1];

    float ax = 0.f, ay = 0.f;
    int i = s;
    for (; i + 3 < t; i += 4) {
        float2 e0 = g_csr[i];
        float2 e1 = g_csr[i + 1];
        float2 e2 = g_csr[i + 2];
        float2 e3 = g_csr[i + 3];
        float2 v0 = *(const float2*)&g_hW[__float_as_int(e0.x) * Dd + d0];
        float2 v1 = *(const float2*)&g_hW[__float_as_int(e1.x) * Dd + d0];
        float2 v2 = *(const float2*)&g_hW[__float_as_int(e2.x) * Dd + d0];
        float2 v3 = *(const float2*)&g_hW[__float_as_int(e3.x) * Dd + d0];
        ax += e0.y * v0.x + e1.y * v1.x;
        ay += e0.y * v0.y + e1.y * v1.y;
        ax += e2.y * v2.x + e3.y * v3.x;
        ay += e2.y * v2.y + e3.y * v3.y;
    }
    for (; i < t; i++) {
        float2 e0 = g_csr[i];
        float2 v0 = *(const float2*)&g_hW[__float_as_int(e0.x) * Dd + d0];
        ax += e0.y * v0.x;
        ay += e0.y * v0.y;
    }

    float di = g_dinv[warp];
    float dd = di * di;
    float2 hw = *(const float2*)&g_hW[warp * Dd + d0];
    float hx = tanhf(ax + dd * hw.x + __ldg(&bias[d0]));
    float hy = tanhf(ay + dd * hw.y + __ldg(&bias[d0 + 1]));

    if (POOL) {
        int g = __ldg(&batch[warp]);
        atomicAdd(&g_gsum[g * Dd + d0], hx);
        atomicAdd(&g_gsum[g * Dd + d0 + 1], hy);
        atomicMax(&g_gmax[g * Dd + d0], fkey(hx));
        atomicMax(&g_gmax[g * Dd + d0 + 1], fkey(hy));
        if (lane == 0) atomicAdd(&g_cnt[g], 1.f);
    } else {
        *(float2*)&g_h[warp * Dd + d0] = make_float2(hx, hy);
    }
}

// out[g] = sum_d gmax[g][d]*Wout[d] + gmean[g][d]*Wout[64+d]  + bout
__global__ void k_out(const float* __restrict__ Wout, const float* __restrict__ bout,
                      float* __restrict__ out) {
    int g = blockIdx.x;
    int d = threadIdx.x;  // 64 threads
    float mx = unfkey(g_gmax[g * Dd + d]);
    float mean = g_gsum[g * Dd + d] / fmaxf(g_cnt[g], 1.f);
    float p = mx * __ldg(&Wout[d]) + mean * __ldg(&Wout[Dd + d]);
#pragma unroll
    for (int o = 16; o > 0; o >>= 1)
        p += __shfl_down_sync(0xffffffffu, p, o);
    __shared__ float s2[2];
    if ((d & 31) == 0) s2[d >> 5] = p;
    __syncthreads();
    if (d == 0) out[g] = s2[0] + s2[1] + __ldg(&bout[0]);
}

// ---------------- launch ----------------------------------------------------

extern "C" void kernel_launch(void* const* d_in, const int* in_sizes, int n_in,
                              void* d_out, int out_size) {
    // ---- bind inputs by element count (robust to metadata ordering) ----
    const float* x = 0; const int* eidx = 0; const int* batch = 0;
    const float* W0 = 0; const float* Wout = 0; const float* bout = 0;
    const float* Ws[3] = {0, 0, 0};    // W1, W2, W3 (size 4096, in order)
    const float* bs[4] = {0, 0, 0, 0}; // b0..b3 (size 64, in order)
    int nW = 0, nb = 0;
    for (int i = 0; i < n_in; i++) {
        int s = in_sizes[i];
        const void* p = d_in[i];
        if      (s == Nn * DIN) x     = (const float*)p;
        else if (s == 2 * Ee)   eidx  = (const int*)p;
        else if (s == Nn)       batch = (const int*)p;
        else if (s == DIN * Dd) W0    = (const float*)p;
        else if (s == Dd * Dd)  { if (nW < 3) Ws[nW++] = (const float*)p; }
        else if (s == Dd)       { if (nb < 4) bs[nb++] = (const float*)p; }
        else if (s == 2 * Dd)   Wout  = (const float*)p;
        else if (s == 1)        bout  = (const float*)p;
    }
    if (!x || !eidx || !batch || !W0 || nW != 3 || nb != 4 || !Wout || !bout) {
        x = (const float*)d_in[0];  eidx = (const int*)d_in[1];
        batch = (const int*)d_in[2];
        W0 = (const float*)d_in[3];  bs[0] = (const float*)d_in[4];
        Ws[0] = (const float*)d_in[5]; bs[1] = (const float*)d_in[6];
        Ws[1] = (const float*)d_in[7]; bs[2] = (const float*)d_in[8];
        Ws[2] = (const float*)d_in[9]; bs[3] = (const float*)d_in[10];
        Wout = (const float*)d_in[11]; bout = (const float*)d_in[12];
    }
    float* out = (float*)d_out;

    const int n = Nn;
    const int e = Ee;
    const int* row = eidx;                 // edge_index[0] = source
    const int* col = eidx + e;             // edge_index[1] = destination

    const int T = 256;
    const int gI   = (Gg * Dd + T - 1) / T;
    const int gE   = (e + T - 1) / T;
    const int gND  = (n * Dd + T - 1) / T;
    const int gAGG = (n * 32 + T - 1) / T;           // one warp per node
    const int gB64 = (n + 63) / 64;

    // prep: degrees, norms, CSR (parallel 3-phase scan)
    k_init<<<gI, T>>>();
    k_deg<<<gE, T>>>(col, e);
    k_dinv<<<(n + T - 1) / T, T>>>(n);
    k_scan1<<<SCAN_NB, SCAN_CHUNK>>>();
    k_scan2<<<1, 256>>>(e);
    k_scan3<<<SCAN_NB, SCAN_CHUNK>>>();
    k_fill<<<gE, T>>>(row, col, e);

    // layer 0 (input GEMM K=9)
    k_gemm_in<<<gND, T>>>(x, W0, n);
    k_agg<0><<<gAGG, T>>>(bs[0], batch, n);

    // layers 1..2
    for (int l = 0; l < 2; l++) {
        k_gemm64<<<gB64, 256>>>(Ws[l], n);
        k_agg<0><<<gAGG, T>>>(bs[l + 1], batch, n);
    }
    // layer 3: fuse pooling
    k_gemm64<<<gB64, 256>>>(Ws[2], n);
    k_agg<1><<<gAGG, T>>>(bs[3], batch, n);

    // readout
    k_out<<<Gg, Dd>>>(Wout, bout, out);

    (void)n_in; (void)out_size;
}

// round 13
// speedup vs baseline: 1.5836x; 1.5836x over previous
#include <cuda_runtime.h>
#include <math.h>

// Problem constants (capacities for static scratch)
#define Nn   50000
#define Ee   800000
#define Gg   1024
#define Dd   64
#define DIN  9

#define SCAN_CHUNK 256
#define SCAN_NB    ((Nn + SCAN_CHUNK - 1) / SCAN_CHUNK)   // 196

// ---------------- scratch (static device globals; no allocation) ------------
static __device__ float    g_hW[Nn * Dd];     // h @ W (pre-aggregation)
static __device__ float    g_h[Nn * Dd];      // layer activations
static __device__ int      g_deg[Nn];         // in-degree (edges only)
static __device__ float    g_dinv[Nn];        // (deg+1)^-1/2
static __device__ int      g_off[Nn + 1];     // CSR offsets (by destination)
static __device__ int      g_pos[Nn];         // fill cursors
static __device__ float2   g_csr[Ee];         // (src as int bits, norm)
static __device__ int      g_bsum[SCAN_NB];   // per-chunk degree sums
static __device__ int      g_boff[SCAN_NB];   // exclusive-scanned chunk offsets
static __device__ float    g_gsum[Gg * Dd];
static __device__ unsigned g_gmax[Gg * Dd];   // order-preserving float keys
static __device__ float    g_cnt[Gg];

// Order-preserving float <-> unsigned key (init 0 == -inf)
__device__ __forceinline__ unsigned fkey(float f) {
    unsigned u = __float_as_uint(f);
    return (u & 0x80000000u) ? ~u : (u | 0x80000000u);
}
__device__ __forceinline__ float unfkey(unsigned k) {
    unsigned u = (k & 0x80000000u) ? (k ^ 0x80000000u) : ~k;
    return __uint_as_float(u);
}

// ---------------- prep kernels ----------------------------------------------

__global__ void k_init() {
    int i = blockIdx.x * blockDim.x + threadIdx.x;
    if (i < Nn) g_deg[i] = 0;
    if (i < Gg * Dd) { g_gsum[i] = 0.f; g_gmax[i] = 0u; }
    if (i < Gg) g_cnt[i] = 0.f;
}

__global__ void k_deg(const int* __restrict__ col, int e) {
    int i = blockIdx.x * blockDim.x + threadIdx.x;
    if (i < e) atomicAdd(&g_deg[col[i]], 1);
}

__global__ void k_dinv(int n) {
    int i = blockIdx.x * blockDim.x + threadIdx.x;
    if (i < n) g_dinv[i] = rsqrtf((float)g_deg[i] + 1.0f);  // +1 = self loop
}

// ---- parallel scan, phase 1: per-chunk sums (256 elems per block) ----------
__global__ void __launch_bounds__(SCAN_CHUNK) k_scan1() {
    __shared__ int ws[SCAN_CHUNK / 32];
    int i = blockIdx.x * SCAN_CHUNK + threadIdx.x;
    int v = (i < Nn) ? g_deg[i] : 0;
    int lane = threadIdx.x & 31, w = threadIdx.x >> 5;
#pragma unroll
    for (int o = 16; o > 0; o >>= 1) v += __shfl_down_sync(~0u, v, o);
    if (lane == 0) ws[w] = v;
    __syncthreads();
    if (threadIdx.x == 0) {
        int s = 0;
#pragma unroll
        for (int k = 0; k < SCAN_CHUNK / 32; k++) s += ws[k];
        g_bsum[blockIdx.x] = s;
    }
}

// ---- phase 2: exclusive scan of chunk sums (single small block) ------------
__global__ void __launch_bounds__(256) k_scan2(int e) {
    __shared__ int wsum[8];
    int lane = threadIdx.x & 31, w = threadIdx.x >> 5;
    int v = (threadIdx.x < SCAN_NB) ? g_bsum[threadIdx.x] : 0;
    int x = v;
#pragma unroll
    for (int o = 1; o < 32; o <<= 1) {
        int y = __shfl_up_sync(~0u, x, o);
        if (lane >= o) x += y;
    }
    if (lane == 31) wsum[w] = x;
    __syncthreads();
    if (w == 0 && lane < 8) {
        int ws = wsum[lane];
#pragma unroll
        for (int o = 1; o < 8; o <<= 1) {
            int y = __shfl_up_sync(0xffu, ws, o);
            if (lane >= o) ws += y;
        }
        wsum[lane] = ws;
    }
    __syncthreads();
    int excl = x - v + (w > 0 ? wsum[w - 1] : 0);
    if (threadIdx.x < SCAN_NB) g_boff[threadIdx.x] = excl;
    if (threadIdx.x == 0) g_off[Nn] = e;
}

// ---- phase 3: per-chunk exclusive scan + chunk offset -> g_off / g_pos -----
__global__ void __launch_bounds__(SCAN_CHUNK) k_scan3() {
    __shared__ int wsum[SCAN_CHUNK / 32];
    int i = blockIdx.x * SCAN_CHUNK + threadIdx.x;
    int v = (i < Nn) ? g_deg[i] : 0;
    int lane = threadIdx.x & 31, w = threadIdx.x >> 5;
    int x = v;
#pragma unroll
    for (int o = 1; o < 32; o <<= 1) {
        int y = __shfl_up_sync(~0u, x, o);
        if (lane >= o) x += y;
    }
    if (lane == 31) wsum[w] = x;
    __syncthreads();
    if (w == 0 && lane < SCAN_CHUNK / 32) {
        int ws = wsum[lane];
#pragma unroll
        for (int o = 1; o < SCAN_CHUNK / 32; o <<= 1) {
            int y = __shfl_up_sync((1u << (SCAN_CHUNK / 32)) - 1u, ws, o);
            if (lane >= o) ws += y;
        }
        wsum[lane] = ws;
    }
    __syncthreads();
    int excl = x - v + (w > 0 ? wsum[w - 1] : 0) + g_boff[blockIdx.x];
    if (i < Nn) { g_off[i] = excl; g_pos[i] = excl; }
}

__global__ void k_fill(const int* __restrict__ row, const int* __restrict__ col, int e) {
    int i = blockIdx.x * blockDim.x + threadIdx.x;
    if (i >= e) return;
    int src = row[i], dst = col[i];
    float nm = g_dinv[src] * g_dinv[dst];
    int pos = atomicAdd(&g_pos[dst], 1);
    g_csr[pos] = make_float2(__int_as_float(src), nm);
}

// ---------------- dense kernels ---------------------------------------------

// x[N,9] @ W0[9,64] -> g_hW
__global__ void k_gemm_in(const float* __restrict__ x, const float* __restrict__ W, int n) {
    int idx = blockIdx.x * blockDim.x + threadIdx.x;
    if (idx >= n * Dd) return;
    int nn = idx >> 6, d = idx & 63;
    float acc = 0.f;
#pragma unroll
    for (int k = 0; k < DIN; k++)
        acc += __ldg(&x[nn * DIN + k]) * __ldg(&W[k * Dd + d]);
    g_hW[idx] = acc;
}

// g_h[N,64] @ W[64,64] -> g_hW ; smem-tiled, 4x4 register tile per thread.
// Reads g_h via device-side symbol (never pass __device__ arrays from host).
__global__ void __launch_bounds__(256) k_gemm64(const float* __restrict__ W, int n) {
    __shared__ float sHT[64][68];  // transposed: sHT[k][r]
    __shared__ float sW[64][68];   // sW[k][d]
    int b0 = blockIdx.x * 64;

    for (int i = threadIdx.x; i < 4096; i += 256) {
        int k = i >> 6, d = i & 63;
        sW[k][d] = W[i];
    }
    for (int i = threadIdx.x; i < 4096; i += 256) {
        int r = i >> 6, k = i & 63;
        int node = b0 + r;
        sHT[k][r] = (node < n) ? g_h[node * 64 + k] : 0.f;
    }
    __syncthreads();

    int tx = threadIdx.x & 15;   // d group
    int ty = threadIdx.x >> 4;   // node group
    int r0 = ty * 4, d0 = tx * 4;

    float acc[4][4] = {};
#pragma unroll
    for (int k = 0; k < 64; k++) {
        float4 av = *(const float4*)&sHT[k][r0];
        float4 bv = *(const float4*)&sW[k][d0];
        float a[4] = {av.x, av.y, av.z, av.w};
        float b[4] = {bv.x, bv.y, bv.z, bv.w};
#pragma unroll
        for (int i = 0; i < 4; i++)
#pragma unroll
            for (int j = 0; j < 4; j++)
                acc[i][j] += a[i] * b[j];
    }

#pragma unroll
    for (int i = 0; i < 4; i++) {
        int node = b0 + r0 + i;
        if (node < n) {
            float4 v = make_float4(acc[i][0], acc[i][1], acc[i][2], acc[i][3]);
            *(float4*)&g_hW[node * 64 + d0] = v;
        }
    }
}

// ---------------- fused gather-aggregate + tanh (+ pooling) -----------------
// one warp per node; lane owns dims {2*lane, 2*lane+1}.
// Edge loop unrolled x2 ONLY: deeper unrolls (x4) regress ~1.4x at full
// occupancy via cross-CTA L1tex-queue contention (MLP_p1 spread, see
// B300_MICROARCH "Multi-CTA spread"). Measured R10 vs R12.
template <int POOL>
__global__ void __launch_bounds__(256) k_agg(const float* __restrict__ bias,
                                             const int* __restrict__ batch, int n) {
    int warp = (blockIdx.x * blockDim.x + threadIdx.x) >> 5;
    if (warp >= n) return;
    int lane = threadIdx.x & 31;
    int d0 = lane * 2;

    int s = g_off[warp];
    int t = g_off[warp + 1];

    float ax = 0.f, ay = 0.f;
    int i = s;
    for (; i + 1 < t; i += 2) {
        float2 e0 = g_csr[i];
        float2 e1 = g_csr[i + 1];
        int s0 = __float_as_int(e0.x);
        int s1 = __float_as_int(e1.x);
        float2 v0 = *(const float2*)&g_hW[s0 * Dd + d0];
        float2 v1 = *(const float2*)&g_hW[s1 * Dd + d0];
        ax += e0.y * v0.x + e1.y * v1.x;
        ay += e0.y * v0.y + e1.y * v1.y;
    }
    if (i < t) {
        float2 e0 = g_csr[i];
        int s0 = __float_as_int(e0.x);
        float2 v0 = *(const float2*)&g_hW[s0 * Dd + d0];
        ax += e0.y * v0.x;
        ay += e0.y * v0.y;
    }

    float di = g_dinv[warp];
    float dd = di * di;
    float2 hw = *(const float2*)&g_hW[warp * Dd + d0];
    float hx = tanhf(ax + dd * hw.x + __ldg(&bias[d0]));
    float hy = tanhf(ay + dd * hw.y + __ldg(&bias[d0 + 1]));

    if (POOL) {
        int g = __ldg(&batch[warp]);
        atomicAdd(&g_gsum[g * Dd + d0], hx);
        atomicAdd(&g_gsum[g * Dd + d0 + 1], hy);
        atomicMax(&g_gmax[g * Dd + d0], fkey(hx));
        atomicMax(&g_gmax[g * Dd + d0 + 1], fkey(hy));
        if (lane == 0) atomicAdd(&g_cnt[g], 1.f);
    } else {
        *(float2*)&g_h[warp * Dd + d0] = make_float2(hx, hy);
    }
}

// out[g] = sum_d gmax[g][d]*Wout[d] + gmean[g][d]*Wout[64+d]  + bout
__global__ void k_out(const float* __restrict__ Wout, const float* __restrict__ bout,
                      float* __restrict__ out) {
    int g = blockIdx.x;
    int d = threadIdx.x;  // 64 threads
    float mx = unfkey(g_gmax[g * Dd + d]);
    float mean = g_gsum[g * Dd + d] / fmaxf(g_cnt[g], 1.f);
    float p = mx * __ldg(&Wout[d]) + mean * __ldg(&Wout[Dd + d]);
#pragma unroll
    for (int o = 16; o > 0; o >>= 1)
        p += __shfl_down_sync(0xffffffffu, p, o);
    __shared__ float s2[2];
    if ((d & 31) == 0) s2[d >> 5] = p;
    __syncthreads();
    if (d == 0) out[g] = s2[0] + s2[1] + __ldg(&bout[0]);
}

// ---------------- launch ----------------------------------------------------

extern "C" void kernel_launch(void* const* d_in, const int* in_sizes, int n_in,
                              void* d_out, int out_size) {
    // ---- bind inputs by element count (robust to metadata ordering) ----
    const float* x = 0; const int* eidx = 0; const int* batch = 0;
    const float* W0 = 0; const float* Wout = 0; const float* bout = 0;
    const float* Ws[3] = {0, 0, 0};    // W1, W2, W3 (size 4096, in order)
    const float* bs[4] = {0, 0, 0, 0}; // b0..b3 (size 64, in order)
    int nW = 0, nb = 0;
    for (int i = 0; i < n_in; i++) {
        int s = in_sizes[i];
        const void* p = d_in[i];
        if      (s == Nn * DIN) x     = (const float*)p;
        else if (s == 2 * Ee)   eidx  = (const int*)p;
        else if (s == Nn)       batch = (const int*)p;
        else if (s == DIN * Dd) W0    = (const float*)p;
        else if (s == Dd * Dd)  { if (nW < 3) Ws[nW++] = (const float*)p; }
        else if (s == Dd)       { if (nb < 4) bs[nb++] = (const float*)p; }
        else if (s == 2 * Dd)   Wout  = (const float*)p;
        else if (s == 1)        bout  = (const float*)p;
    }
    if (!x || !eidx || !batch || !W0 || nW != 3 || nb != 4 || !Wout || !bout) {
        x = (const float*)d_in[0];  eidx = (const int*)d_in[1];
        batch = (const int*)d_in[2];
        W0 = (const float*)d_in[3];  bs[0] = (const float*)d_in[4];
        Ws[0] = (const float*)d_in[5]; bs[1] = (const float*)d_in[6];
        Ws[1] = (const float*)d_in[7]; bs[2] = (const float*)d_in[8];
        Ws[2] = (const float*)d_in[9]; bs[3] = (const float*)d_in[10];
        Wout = (const float*)d_in[11]; bout = (const float*)d_in[12];
    }
    float* out = (float*)d_out;

    const int n = Nn;
    const int e = Ee;
    const int* row = eidx;                 // edge_index[0] = source
    const int* col = eidx + e;             // edge_index[1] = destination

    const int T = 256;
    const int gI   = (Gg * Dd + T - 1) / T;
    const int gE   = (e + T - 1) / T;
    const int gND  = (n * Dd + T - 1) / T;
    const int gAGG = (n * 32 + T - 1) / T;           // one warp per node
    const int gB64 = (n + 63) / 64;

    // prep: degrees, norms, CSR (parallel 3-phase scan)
    k_init<<<gI, T>>>();
    k_deg<<<gE, T>>>(col, e);
    k_dinv<<<(n + T - 1) / T, T>>>(n);
    k_scan1<<<SCAN_NB, SCAN_CHUNK>>>();
    k_scan2<<<1, 256>>>(e);
    k_scan3<<<SCAN_NB, SCAN_CHUNK>>>();
    k_fill<<<gE, T>>>(row, col, e);

    // layer 0 (input GEMM K=9)
    k_gemm_in<<<gND, T>>>(x, W0, n);
    k_agg<0><<<gAGG, T>>>(bs[0], batch, n);

    // layers 1..2
    for (int l = 0; l < 2; l++) {
        k_gemm64<<<gB64, 256>>>(Ws[l], n);
        k_agg<0><<<gAGG, T>>>(bs[l + 1], batch, n);
    }
    // layer 3: fuse pooling
    k_gemm64<<<gB64, 256>>>(Ws[2], n);
    k_agg<1><<<gAGG, T>>>(bs[3], batch, n);

    // readout
    k_out<<<Gg, Dd>>>(Wout, bout, out);

    (void)n_in; (void)out_size;
}